// round 3
// baseline (speedup 1.0000x reference)
#include <cuda_runtime.h>

#define FULLMASK 0xffffffffu

// All shuffles use width=16: lanes 0-15 and 16-31 of a warp handle two
// independent rows.

__device__ __forceinline__ float max16(float v) {
#pragma unroll
  for (int m = 8; m; m >>= 1) v = fmaxf(v, __shfl_xor_sync(FULLMASK, v, m, 16));
  return v;
}

__device__ __forceinline__ float sum16(float v) {
#pragma unroll
  for (int m = 8; m; m >>= 1) v += __shfl_xor_sync(FULLMASK, v, m, 16);
  return v;
}

// For one 256-float byte-distribution vector:
//   hs = sum of elements [16l, 16l+16)  -> high-nibble sum for nibble index l
//   ls = sum of elements l, l+16, ...   -> low-nibble sum for nibble index l
// High path: 4x LDG.128 (lane-local block). Low path: 16 coalesced scalar
// loads (same lines, L1 hits) -- avoids any cross-lane reduction.
__device__ __forceinline__ void load_sums(const float* __restrict__ p, int l,
                                          float& hs, float& ls) {
  const float4* p4 = reinterpret_cast<const float4*>(p) + 4 * l;
  float4 x0 = p4[0], x1 = p4[1], x2 = p4[2], x3 = p4[3];
  hs = ((x0.x + x0.y) + (x0.z + x0.w)) + ((x1.x + x1.y) + (x1.z + x1.w)) +
       ((x2.x + x2.y) + (x2.z + x2.w)) + ((x3.x + x3.y) + (x3.z + x3.w));
  float s = 0.f;
#pragma unroll
  for (int j = 0; j < 16; j++) s += p[16 * j + l];
  ls = s;
}

// Nibble add with separable softmax:
//   p = softmax(100*x) (x) softmax(100*y); q[t] = conv(pX,pY)[t], t in [0,30]
//   s0[s] = q[s] + q[s+16]            (carry_in = 0 branch)
//   s1[s] = q[s-1] + q[s+15]          (carry_in = 1 branch)
//   C0 = sum_{t>=16} q[t], C1 = C0 + q[15]
// Lane l ends with s0[l], s1[l]; C0/C1 are uniform across the 16 lanes.
__device__ __forceinline__ void nib_add(float x, float y, int l,
                                        float& s0, float& s1,
                                        float& C0, float& C1) {
  float mx = max16(x);
  float ex = __expf(100.f * (x - mx));   // unnormalized softmax numerators
  float Zx = sum16(ex);
  float my = max16(y);
  float ey = __expf(100.f * (y - my));
  float Zy = sum16(ey);

  // lane l accumulates q[l] (A<=l) and q[l+16] (A>l); q[31] = 0 naturally.
  float qlo = 0.f, qhi = 0.f;
#pragma unroll
  for (int A = 0; A < 16; A++) {
    float bA = __shfl_sync(FULLMASK, ex, A, 16);
    float r  = __shfl_sync(FULLMASK, ey, (l - A) & 15, 16);
    if (A <= l) qlo = fmaf(bA, r, qlo);
    else        qhi = fmaf(bA, r, qhi);
  }

  float inv = 1.0f / (Zx * Zy);          // joint softmax normalization
  float qs  = qlo + qhi;
  s0 = qs * inv;                                                  // q[l]+q[l+16]
  s1 = __shfl_sync(FULLMASK, qs, (l + 15) & 15, 16) * inv;        // q[l-1]+q[l+15]
  C0 = sum16(qhi) * inv;                                          // P(A+B > 15)
  C1 = C0 + __shfl_sync(FULLMASK, qlo, 15, 16) * inv;             // + q[15]
}

__global__ __launch_bounds__(256) void neural_alu_kernel(
    const float* __restrict__ A, const float* __restrict__ B,
    float* __restrict__ O, int nrows) {
  int gid = blockIdx.x * blockDim.x + threadIdx.x;
  int row = gid >> 4;
  int l   = gid & 15;
  if (row >= nrows) return;

  const float* a = A + (size_t)row * 1024;
  const float* b = B + (size_t)row * 1024;
  float*       o = O + (size_t)row * 1024;

  // Carry-independent results for all 8 nibble adds (low/high of 4 bytes).
  float s0l[4], s1l[4], s0h[4], s1h[4], c0[8], c1[8];

#pragma unroll
  for (int i = 0; i < 4; i++) {
    float ah, al, bh, bl;
    load_sums(a + i * 256, l, ah, al);
    load_sums(b + i * 256, l, bh, bl);
    nib_add(al, bl, l, s0l[i], s1l[i], c0[2 * i],     c1[2 * i]);
    nib_add(ah, bh, l, s0h[i], s1h[i], c0[2 * i + 1], c1[2 * i + 1]);
  }

  // Ripple-carry chain: carry enters only through softmax(100*carry), i.e.
  // pc1 = sigmoid(100*(u1-u0)). u1 = P(carry=1), u0 = 1-u1. Initial carry
  // one-hot at 0 -> exp(+100) = inf -> pc1 = 0 (matches reference to <1e-40).
  float pc[8];
  float u1 = 0.f;
#pragma unroll
  for (int k = 0; k < 8; k++) {
    float e  = __expf(100.f * (1.f - 2.f * u1));  // exp(100*(u0-u1))
    float p1 = 1.f / (1.f + e);                   // inf-safe: 1/(1+inf)=0
    pc[k] = p1;
    u1 = c0[k] + (c1[k] - c0[k]) * p1;
  }

  // Output: _n2b is an outer product of two 16-softmaxes.
  // out[16h + m] = eH[h] * eL[m] / (Zh*Zl); lane l writes block [16l, 16l+16).
#pragma unroll
  for (int i = 0; i < 4; i++) {
    float sl = s0l[i] + (s1l[i] - s0l[i]) * pc[2 * i];
    float sh = s0h[i] + (s1h[i] - s0h[i]) * pc[2 * i + 1];

    float ml = max16(sl);
    float el = __expf(100.f * (sl - ml));
    float Zl = sum16(el);
    float mh = max16(sh);
    float eh = __expf(100.f * (sh - mh));
    float Zh = sum16(eh);

    float scale = eh / (Zh * Zl);
    float buf[16];
#pragma unroll
    for (int m = 0; m < 16; m++)
      buf[m] = scale * __shfl_sync(FULLMASK, el, m, 16);

    float4* op = reinterpret_cast<float4*>(o + i * 256) + 4 * l;
    op[0] = make_float4(buf[0],  buf[1],  buf[2],  buf[3]);
    op[1] = make_float4(buf[4],  buf[5],  buf[6],  buf[7]);
    op[2] = make_float4(buf[8],  buf[9],  buf[10], buf[11]);
    op[3] = make_float4(buf[12], buf[13], buf[14], buf[15]);
  }
}

extern "C" void kernel_launch(void* const* d_in, const int* in_sizes, int n_in,
                              void* d_out, int out_size) {
  const float* a = (const float*)d_in[0];
  const float* b = (const float*)d_in[1];
  float*       o = (float*)d_out;
  int nrows = in_sizes[0] / 1024;            // (B,4,256) -> B rows of 1024
  int threads = 256;                          // 16 rows per block
  int blocks = (nrows * 16 + threads - 1) / threads;
  neural_alu_kernel<<<blocks, threads>>>(a, b, o, nrows);
}

// round 7
// speedup vs baseline: 1.1839x; 1.1839x over previous
#include <cuda_runtime.h>

#define FULLMASK 0xffffffffu

// Two rows per warp: lanes 0-15 / 16-31 are independent 16-lane groups.
// All shuffles use width=16 so the halves never interact.

__device__ __forceinline__ float max16(float v) {
#pragma unroll
  for (int m = 8; m; m >>= 1) v = fmaxf(v, __shfl_xor_sync(FULLMASK, v, m, 16));
  return v;
}

__device__ __forceinline__ float sum16(float v) {
#pragma unroll
  for (int m = 8; m; m >>= 1) v += __shfl_xor_sync(FULLMASK, v, m, 16);
  return v;
}

// Load one 256-float byte-distribution vector (16 rows x 16 cols, row-major).
// Lane l holds row l (u[0..15] = p[16l .. 16l+15]).
//   hs = row-l sum   (lane-local adds)
//   ls = col-l sum   (butterfly reduce-scatter: 15 shfl, replaces the old
//        stride-16 LDG re-read that doubled L1 data traffic)
__device__ __forceinline__ void load_sums(const float* __restrict__ p, int l,
                                          float& hs, float& ls) {
  const float4* p4 = reinterpret_cast<const float4*>(p) + 4 * l;
  float4 x0 = p4[0], x1 = p4[1], x2 = p4[2], x3 = p4[3];
  float u[16] = {x0.x, x0.y, x0.z, x0.w, x1.x, x1.y, x1.z, x1.w,
                 x2.x, x2.y, x2.z, x2.w, x3.x, x3.y, x3.z, x3.w};
  hs = ((u[0] + u[1]) + (u[2] + u[3])) + ((u[4] + u[5]) + (u[6] + u[7])) +
       ((u[8] + u[9]) + (u[10] + u[11])) + ((u[12] + u[13]) + (u[14] + u[15]));

  // Reduce-scatter: at each stage, keep entries for columns whose bit matches
  // my lane bit, send the rest to the xor-partner, add what arrives.
  bool b8 = (l & 8) != 0;
  float w[8];
#pragma unroll
  for (int k = 0; k < 8; k++) {
    float send = b8 ? u[k] : u[k + 8];
    float keep = b8 ? u[k + 8] : u[k];
    w[k] = keep + __shfl_xor_sync(FULLMASK, send, 8, 16);
  }
  bool b4 = (l & 4) != 0;
  float x[4];
#pragma unroll
  for (int k = 0; k < 4; k++) {
    float send = b4 ? w[k] : w[k + 4];
    float keep = b4 ? w[k + 4] : w[k];
    x[k] = keep + __shfl_xor_sync(FULLMASK, send, 4, 16);
  }
  bool b2 = (l & 2) != 0;
  float y[2];
#pragma unroll
  for (int k = 0; k < 2; k++) {
    float send = b2 ? x[k] : x[k + 2];
    float keep = b2 ? x[k + 2] : x[k];
    y[k] = keep + __shfl_xor_sync(FULLMASK, send, 2, 16);
  }
  bool b1 = (l & 1) != 0;
  float send = b1 ? y[0] : y[1];
  float keep = b1 ? y[1] : y[0];
  ls = keep + __shfl_xor_sync(FULLMASK, send, 1, 16);
}

// Separable-softmax nibble add.
//   ex,ey = unnormalized softmax numerators; q = conv(ex,ey), t in [0,30]
//   Z = sum q = Zx*Zy (single fused reduction)
//   s0[l] = (q[l]+q[l+16])/Z   (carry_in = 0)
//   s1[l] = s0[(l-1)&15]       (carry_in = 1)
//   C0 = P(t>15), C1 = C0 + q[15]/Z
__device__ __forceinline__ void nib_add(float xin, float yin, int l,
                                        float& s0, float& s1,
                                        float& C0, float& C1) {
  float ex = __expf(100.f * (xin - max16(xin)));
  float ey = __expf(100.f * (yin - max16(yin)));

  float qlo = 0.f, qhi = 0.f;  // lane l: q[l] (A<=l) and q[l+16] (A>l)
#pragma unroll
  for (int A = 0; A < 16; A++) {
    float bA = __shfl_sync(FULLMASK, ex, A, 16);
    float r  = __shfl_sync(FULLMASK, ey, (l - A) & 15, 16);
    if (A <= l) qlo = fmaf(bA, r, qlo);
    else        qhi = fmaf(bA, r, qhi);
  }
  float qs  = qlo + qhi;
  float inv = 1.0f / sum16(qs);                       // = 1/(Zx*Zy), >= ~1
  s0 = qs * inv;
  s1 = __shfl_sync(FULLMASK, qs, (l + 15) & 15, 16) * inv;
  C0 = sum16(qhi) * inv;
  C1 = fmaf(__shfl_sync(FULLMASK, qlo, 15, 16), inv, C0);
}

__global__ __launch_bounds__(256) void neural_alu_kernel(
    const float* __restrict__ A, const float* __restrict__ B,
    float* __restrict__ O, int nrows) {
  int gid = blockIdx.x * blockDim.x + threadIdx.x;
  int row = gid >> 4;
  int l   = gid & 15;
  if (row >= nrows) return;

  const float* a = A + (size_t)row * 1024;
  const float* b = B + (size_t)row * 1024;
  float*       o = O + (size_t)row * 1024;

  // Carry-independent results for all 8 nibble adds (low/high of 4 bytes).
  float s0l[4], s1l[4], s0h[4], s1h[4], c0[8], c1[8];

#pragma unroll
  for (int i = 0; i < 4; i++) {
    float ah, al, bh, bl;
    load_sums(a + i * 256, l, ah, al);
    load_sums(b + i * 256, l, bh, bl);
    nib_add(al, bl, l, s0l[i], s1l[i], c0[2 * i],     c1[2 * i]);
    nib_add(ah, bh, l, s0h[i], s1h[i], c0[2 * i + 1], c1[2 * i + 1]);
  }

  // Ripple-carry chain: pc1 = sigmoid(100*(u1-u0)). Initial carry one-hot at
  // 0 -> exp(+100) = inf -> p1 = 1/(1+inf) = 0 exactly (matches reference).
  float pc[8];
  float u1 = 0.f;
#pragma unroll
  for (int k = 0; k < 8; k++) {
    float e  = __expf(fmaf(-200.f, u1, 100.f));  // exp(100*(u0-u1))
    float p1 = 1.f / (1.f + e);
    pc[k] = p1;
    u1 = fmaf(c1[k] - c0[k], p1, c0[k]);
  }

  // Output: _n2b = outer product of two 16-softmaxes. Inputs s in [0,1], so a
  // fixed -50 shift keeps exp in [e-50, e50] -- no max reduction needed.
#pragma unroll
  for (int i = 0; i < 4; i++) {
    float sl = fmaf(s1l[i] - s0l[i], pc[2 * i],     s0l[i]);
    float sh = fmaf(s1h[i] - s0h[i], pc[2 * i + 1], s0h[i]);

    float el = __expf(fmaf(100.f, sl, -50.f));
    float eh = __expf(fmaf(100.f, sh, -50.f));
    float invZl = 1.0f / sum16(el);
    float invZh = 1.0f / sum16(eh);

    // scale = eh/(Zh*Zl); grouped to avoid overflow in Zh*Zl
    float scale = (eh * invZh) * invZl;
    float buf[16];
#pragma unroll
    for (int m = 0; m < 16; m++)
      buf[m] = scale * __shfl_sync(FULLMASK, el, m, 16);

    float4* op = reinterpret_cast<float4*>(o + i * 256) + 4 * l;
    op[0] = make_float4(buf[0],  buf[1],  buf[2],  buf[3]);
    op[1] = make_float4(buf[4],  buf[5],  buf[6],  buf[7]);
    op[2] = make_float4(buf[8],  buf[9],  buf[10], buf[11]);
    op[3] = make_float4(buf[12], buf[13], buf[14], buf[15]);
  }
}

extern "C" void kernel_launch(void* const* d_in, const int* in_sizes, int n_in,
                              void* d_out, int out_size) {
  const float* a = (const float*)d_in[0];
  const float* b = (const float*)d_in[1];
  float*       o = (float*)d_out;
  int nrows = in_sizes[0] / 1024;            // (B,4,256) -> B rows of 1024
  int threads = 256;                          // 16 rows per block
  int blocks = (nrows * 16 + threads - 1) / threads;
  neural_alu_kernel<<<blocks, threads>>>(a, b, o, nrows);
}

// round 8
// speedup vs baseline: 1.2507x; 1.0564x over previous
#include <cuda_runtime.h>

#define FULLMASK 0xffffffffu

// Two rows per warp: lanes 0-15 / 16-31 are independent 16-lane groups.
// All shuffles use width=16 so the halves never interact.

__device__ __forceinline__ float max16(float v) {
#pragma unroll
  for (int m = 8; m; m >>= 1) v = fmaxf(v, __shfl_xor_sync(FULLMASK, v, m, 16));
  return v;
}

__device__ __forceinline__ float sum16(float v) {
#pragma unroll
  for (int m = 8; m; m >>= 1) v += __shfl_xor_sync(FULLMASK, v, m, 16);
  return v;
}

// Load one 256-float byte-distribution vector (16 rows x 16 cols, row-major).
// Lane l holds row l.  hs = row-l sum (lane-local).  ls = col-l sum via
// butterfly reduce-scatter (15 shfl; no duplicate global re-read).
__device__ __forceinline__ void load_sums(const float* __restrict__ p, int l,
                                          float& hs, float& ls) {
  const float4* p4 = reinterpret_cast<const float4*>(p) + 4 * l;
  float4 x0 = p4[0], x1 = p4[1], x2 = p4[2], x3 = p4[3];
  float u[16] = {x0.x, x0.y, x0.z, x0.w, x1.x, x1.y, x1.z, x1.w,
                 x2.x, x2.y, x2.z, x2.w, x3.x, x3.y, x3.z, x3.w};
  hs = ((u[0] + u[1]) + (u[2] + u[3])) + ((u[4] + u[5]) + (u[6] + u[7])) +
       ((u[8] + u[9]) + (u[10] + u[11])) + ((u[12] + u[13]) + (u[14] + u[15]));

  bool b8 = (l & 8) != 0;
  float w[8];
#pragma unroll
  for (int k = 0; k < 8; k++) {
    float send = b8 ? u[k] : u[k + 8];
    float keep = b8 ? u[k + 8] : u[k];
    w[k] = keep + __shfl_xor_sync(FULLMASK, send, 8, 16);
  }
  bool b4 = (l & 4) != 0;
  float x[4];
#pragma unroll
  for (int k = 0; k < 4; k++) {
    float send = b4 ? w[k] : w[k + 4];
    float keep = b4 ? w[k + 4] : w[k];
    x[k] = keep + __shfl_xor_sync(FULLMASK, send, 4, 16);
  }
  bool b2 = (l & 2) != 0;
  float y[2];
#pragma unroll
  for (int k = 0; k < 2; k++) {
    float send = b2 ? x[k] : x[k + 2];
    float keep = b2 ? x[k + 2] : x[k];
    y[k] = keep + __shfl_xor_sync(FULLMASK, send, 2, 16);
  }
  bool b1 = (l & 1) != 0;
  float send = b1 ? y[0] : y[1];
  float keep = b1 ? y[1] : y[0];
  ls = keep + __shfl_xor_sync(FULLMASK, send, 1, 16);
}

// Separable-softmax nibble add.
//   ex,ey = unnormalized softmax numerators; q = conv(ex,ey), t in [0,30]
//   Z = sum q = Zx*Zy (single fused reduction)
//   s0[l] = (q[l]+q[l+16])/Z (cin=0), s1[l] = s0[(l-1)&15] (cin=1)
//   C0 = P(t>15), C1 = C0 + q[15]/Z
__device__ __forceinline__ void nib_add(float xin, float yin, int l,
                                        float& s0, float& s1,
                                        float& C0, float& C1) {
  float ex = __expf(100.f * (xin - max16(xin)));
  float ey = __expf(100.f * (yin - max16(yin)));

  float qlo = 0.f, qhi = 0.f;  // lane l: q[l] (A<=l) and q[l+16] (A>l)
#pragma unroll
  for (int A = 0; A < 16; A++) {
    float bA = __shfl_sync(FULLMASK, ex, A, 16);
    float r  = __shfl_sync(FULLMASK, ey, (l - A) & 15, 16);
    if (A <= l) qlo = fmaf(bA, r, qlo);
    else        qhi = fmaf(bA, r, qhi);
  }
  float qs  = qlo + qhi;
  float inv = 1.0f / sum16(qs);                       // = 1/(Zx*Zy)
  s0 = qs * inv;
  s1 = __shfl_sync(FULLMASK, qs, (l + 15) & 15, 16) * inv;
  C0 = sum16(qhi) * inv;
  C1 = fmaf(__shfl_sync(FULLMASK, qlo, 15, 16), inv, C0);
}

// Streaming per-byte pipeline: only the scalar carry prob u1 is live across
// bytes, so no cross-byte register arrays -> <=64 regs -> 4 blocks/SM.
__global__ __launch_bounds__(256, 4) void neural_alu_kernel(
    const float* __restrict__ A, const float* __restrict__ B,
    float* __restrict__ O, int nrows) {
  int gid = blockIdx.x * blockDim.x + threadIdx.x;
  int row = gid >> 4;
  int l   = gid & 15;
  if (row >= nrows) return;

  const float* a = A + (size_t)row * 1024;
  const float* b = B + (size_t)row * 1024;
  float*       o = O + (size_t)row * 1024;

  float u1 = 0.f;  // P(carry=1); initial one-hot carry_zero -> 0 exactly

#pragma unroll
  for (int i = 0; i < 4; i++) {
    float ah, al, bh, bl;
    load_sums(a + i * 256, l, ah, al);
    load_sums(b + i * 256, l, bh, bl);

    float s0l, s1l, c0l, c1l, s0h, s1h, c0h, c1h;
    nib_add(al, bl, l, s0l, s1l, c0l, c1l);
    nib_add(ah, bh, l, s0h, s1h, c0h, c1h);

    // carry into low nibble: pc = sigmoid(100*(u1-u0)); exp(+100)=inf -> 0.
    float pcl = 1.f / (1.f + __expf(fmaf(-200.f, u1, 100.f)));
    u1 = fmaf(c1l - c0l, pcl, c0l);
    // carry into high nibble
    float pch = 1.f / (1.f + __expf(fmaf(-200.f, u1, 100.f)));
    u1 = fmaf(c1h - c0h, pch, c0h);

    float sl = fmaf(s1l - s0l, pcl, s0l);
    float sh = fmaf(s1h - s0h, pch, s0h);

    // _n2b = outer product of two 16-softmaxes. s in [0,1] -> fixed -50 shift
    // keeps exp in float range; no max reduction needed.
    float el = __expf(fmaf(100.f, sl, -50.f));
    float eh = __expf(fmaf(100.f, sh, -50.f));
    float invZl = 1.0f / sum16(el);
    float invZh = 1.0f / sum16(eh);

    float scale = (eh * invZh) * invZl;   // eh/(Zh*Zl), grouped vs overflow
    float buf[16];
#pragma unroll
    for (int m = 0; m < 16; m++)
      buf[m] = scale * __shfl_sync(FULLMASK, el, m, 16);

    float4* op = reinterpret_cast<float4*>(o + i * 256) + 4 * l;
    op[0] = make_float4(buf[0],  buf[1],  buf[2],  buf[3]);
    op[1] = make_float4(buf[4],  buf[5],  buf[6],  buf[7]);
    op[2] = make_float4(buf[8],  buf[9],  buf[10], buf[11]);
    op[3] = make_float4(buf[12], buf[13], buf[14], buf[15]);
  }
}

extern "C" void kernel_launch(void* const* d_in, const int* in_sizes, int n_in,
                              void* d_out, int out_size) {
  const float* a = (const float*)d_in[0];
  const float* b = (const float*)d_in[1];
  float*       o = (float*)d_out;
  int nrows = in_sizes[0] / 1024;            // (B,4,256) -> B rows of 1024
  int threads = 256;                          // 16 rows per block
  int blocks = (nrows * 16 + threads - 1) / threads;
  neural_alu_kernel<<<blocks, threads>>>(a, b, o, nrows);
}